// round 10
// baseline (speedup 1.0000x reference)
#include <cuda_runtime.h>
#include <math.h>

// ---------------------------------------------------------------------------
// Decoder_50775103373422: 2-layer LSTM (B=64, H=2048, IN=OUT=66, T=25) with
// hardtanh output fed back as next input.
// R7: 256-thread cell CTAs with split-kk dual warp-groups (2 warps/SMSP),
//     cp.async 3-stage pipeline; tiled FC (16 b-groups x 6 n-groups).
// ---------------------------------------------------------------------------

namespace {
constexpr int B_   = 64;    // batch
constexpr int H_   = 2048;  // hidden
constexpr int IN_  = 66;    // input / output features
constexpr int T_   = 25;    // timesteps
constexpr int XPAD = 72;    // padded input width (multiple of 8)
constexpr int JT   = 16;    // hidden units per CTA  -> grid = 2048/16 = 128
constexpr int SLD  = 76;    // smem row stride in floats (conflict-free, 16B-aligned)
constexpr int NTH  = 256;   // threads per cell CTA (8 warps: 2 kk-groups x 2x2)
constexpr int STG  = 3;     // cp.async pipeline stages
constexpr int TILE_WORDS = B_ * SLD;                       // floats per A or B stage
constexpr int SMEM_BYTES = STG * 2 * TILE_WORDS * 4;       // 116736 B dynamic smem
}

// Scratch state (allocation-free rule: __device__ globals), 16B-aligned for cp.async
__device__ __align__(16) float g_x[2][B_][XPAD];   // fed-back input, ping-pong
__device__ __align__(16) float g_h[2][2][B_][H_];  // [layer][parity][b][j]
__device__ __align__(16) float g_c[2][B_][H_];     // in-place per launch

__device__ __forceinline__ unsigned u32smem(const void* p) {
    return (unsigned)__cvta_generic_to_shared(p);
}
__device__ __forceinline__ void cpasync16(unsigned s, const void* g) {
    asm volatile("cp.async.cg.shared.global [%0], [%1], 16;\n" :: "r"(s), "l"(g));
}
__device__ __forceinline__ void cpcommit() {
    asm volatile("cp.async.commit_group;\n" ::);
}
template <int N>
__device__ __forceinline__ void cpwait() {
    asm volatile("cp.async.wait_group %0;\n" :: "n"(N));
}

__device__ __forceinline__ void mma8(float* d,
                                     unsigned a0, unsigned a1, unsigned a2, unsigned a3,
                                     unsigned b0, unsigned b1) {
    asm volatile(
        "mma.sync.aligned.m16n8k8.row.col.f32.tf32.tf32.f32 "
        "{%0,%1,%2,%3}, {%4,%5,%6,%7}, {%8,%9}, {%0,%1,%2,%3};"
        : "+f"(d[0]), "+f"(d[1]), "+f"(d[2]), "+f"(d[3])
        : "r"(a0), "r"(a1), "r"(a2), "r"(a3), "r"(b0), "r"(b1));
}

// Issue cp.async for one 64x64 fp32 tile of A and of B into a stage (256 thr).
__device__ __forceinline__ void issue_tile(float* sA, float* sB,
                                           const float* __restrict__ A,
                                           const float* __restrict__ W,
                                           int j0, int k0, int tid) {
    const int r = tid >> 4;            // 0..15
    const int c = (tid & 15) << 2;     // 0..60
#pragma unroll
    for (int p = 0; p < 4; p++) {
        int row = r + p * 16;
        cpasync16(u32smem(sA + row * SLD + c), A + (size_t)row * H_ + k0 + c);
    }
#pragma unroll
    for (int p = 0; p < 4; p++) {
        int n = r + p * 16;
        int R = (n >> 4) * H_ + j0 + (n & 15);   // gate-major weight row
        cpasync16(u32smem(sB + n * SLD + c), W + (size_t)R * H_ + k0 + c);
    }
}

// Warp computes kk in [KK0, KK1) of a tile with warp tile m32 x n32 (2x2 grid).
// As/Bs hold raw fp32 bits; HMMA.TF32 truncates mantissa in hardware.
template <int KK0, int KK1>
__device__ __forceinline__ void tile_compute(const unsigned* __restrict__ As,
                                             const unsigned* __restrict__ Bs,
                                             float (&acc)[2][4][4],
                                             int wm, int wn, int gID, int tig) {
#pragma unroll
    for (int kk = KK0; kk < KK1; kk += 8) {
        unsigned a[2][4];
#pragma unroll
        for (int am = 0; am < 2; am++) {
            int r0 = (wm * 32 + am * 16 + gID) * SLD;
            a[am][0] = As[r0 + kk + tig];
            a[am][1] = As[r0 + 8 * SLD + kk + tig];
            a[am][2] = As[r0 + kk + tig + 4];
            a[am][3] = As[r0 + 8 * SLD + kk + tig + 4];
        }
#pragma unroll
        for (int t8 = 0; t8 < 4; t8++) {
            int n = (wn * 32 + t8 * 8 + gID) * SLD;
            unsigned b0 = Bs[n + kk + tig];
            unsigned b1 = Bs[n + kk + tig + 4];
#pragma unroll
            for (int am = 0; am < 2; am++)
                mma8(acc[am][t8], a[am][0], a[am][1], a[am][2], a[am][3], b0, b1);
        }
    }
}

// One LSTM cell step for one layer. CTA owns hidden units [j0, j0+16) across
// all 4 gates (64 N-columns) and the full batch (M=64). Two kk warp-groups
// split each K-tile; epilogue reduces the halves and does the cell update.
__global__ void __launch_bounds__(NTH, 1)
lstm_cell_kernel(const float* __restrict__ Wih, const float* __restrict__ Whh,
                 const float* __restrict__ bih, const float* __restrict__ bhh,
                 int layer, int parity, int use_x) {
    extern __shared__ __align__(16) float smem_raw[];
    float* sA[STG];
    float* sB[STG];
#pragma unroll
    for (int st = 0; st < STG; st++) {
        sA[st] = smem_raw + st * 2 * TILE_WORDS;
        sB[st] = sA[st] + TILE_WORDS;
    }

    const int tid  = threadIdx.x;
    const int j0   = blockIdx.x * JT;
    const int warp = tid >> 5, lane = tid & 31;
    const int kg   = warp >> 2;          // kk-group: 0 or 1
    const int w2   = warp & 3;           // warp within group
    const int wm = w2 >> 1, wn = w2 & 1;
    const int gID = lane >> 2, tig = lane & 3;

    float acc[2][4][4];
#pragma unroll
    for (int a = 0; a < 2; a++)
#pragma unroll
        for (int b = 0; b < 4; b++)
#pragma unroll
            for (int c = 0; c < 4; c++) acc[a][b][c] = 0.f;

    // ---- layer0 only: x @ Wih0^T  (K=66 padded to 72, scalar fills) ----
    if (use_x) {
        const float* A = &g_x[parity][0][0];
        for (int idx = tid; idx < B_ * XPAD; idx += NTH) {
            int r = idx / XPAD, k = idx - r * XPAD;
            sA[0][r * SLD + k] = A[idx];
        }
        for (int idx = tid; idx < B_ * XPAD; idx += NTH) {
            int n = idx / XPAD, k = idx - n * XPAD;
            int R = (n >> 4) * H_ + j0 + (n & 15);
            sB[0][n * SLD + k] = (k < IN_) ? Wih[R * IN_ + k] : 0.f;
        }
        __syncthreads();
        if (kg == 0)
            tile_compute<0, 40>((const unsigned*)sA[0], (const unsigned*)sB[0],
                                acc, wm, wn, gID, tig);
        else
            tile_compute<40, XPAD>((const unsigned*)sA[0], (const unsigned*)sB[0],
                                   acc, wm, wn, gID, tig);
        __syncthreads();
    }

    // ---- K=2048 segments, 3-stage cp.async pipeline ----
    const float* Aseg[2];
    const float* Wseg[2];
    int nseg;
    if (use_x) {                                 // layer 0: h0_prev @ Whh0^T
        Aseg[0] = &g_h[0][parity][0][0];     Wseg[0] = Whh;  nseg = 1;
    } else {                                     // layer 1: h0_new @ Wih1^T + h1_prev @ Whh1^T
        Aseg[0] = &g_h[0][parity ^ 1][0][0]; Wseg[0] = Wih;
        Aseg[1] = &g_h[1][parity][0][0];     Wseg[1] = Whh;
        nseg = 2;
    }
    const int total = nseg * 32;

    // Prologue: fill STG-1 stages.
#pragma unroll
    for (int s = 0; s < STG - 1; s++) {
        issue_tile(sA[s], sB[s], Aseg[s >> 5], Wseg[s >> 5], j0, (s & 31) * 64, tid);
        cpcommit();
    }

    for (int s = 0; s < total; s++) {
        cpwait<STG - 2>();          // stage s landed
        __syncthreads();
        int nx = s + STG - 1;
        if (nx < total) {
            issue_tile(sA[nx % STG], sB[nx % STG],
                       Aseg[nx >> 5], Wseg[nx >> 5], j0, (nx & 31) * 64, tid);
        }
        cpcommit();                 // keep group accounting aligned
        int cs = s % STG;
        if (kg == 0)
            tile_compute<0, 32>((const unsigned*)sA[cs], (const unsigned*)sB[cs],
                                acc, wm, wn, gID, tig);
        else
            tile_compute<32, 64>((const unsigned*)sA[cs], (const unsigned*)sB[cs],
                                 acc, wm, wn, gID, tig);
    }
    __syncthreads();

    // ---- epilogue: group0 stores frags, group1 adds, then fused cell update ----
    float* Gs = smem_raw;           // 64 x 65 fp32 overlay
    if (kg == 0) {
#pragma unroll
        for (int am = 0; am < 2; am++)
#pragma unroll
            for (int t8 = 0; t8 < 4; t8++) {
                int r0 = wm * 32 + am * 16 + gID;
                int n  = wn * 32 + t8 * 8 + (tig << 1);
                Gs[n * 65 + r0]           = acc[am][t8][0];
                Gs[(n + 1) * 65 + r0]     = acc[am][t8][1];
                Gs[n * 65 + r0 + 8]       = acc[am][t8][2];
                Gs[(n + 1) * 65 + r0 + 8] = acc[am][t8][3];
            }
    }
    __syncthreads();
    if (kg == 1) {
#pragma unroll
        for (int am = 0; am < 2; am++)
#pragma unroll
            for (int t8 = 0; t8 < 4; t8++) {
                int r0 = wm * 32 + am * 16 + gID;
                int n  = wn * 32 + t8 * 8 + (tig << 1);
                Gs[n * 65 + r0]           += acc[am][t8][0];
                Gs[(n + 1) * 65 + r0]     += acc[am][t8][1];
                Gs[n * 65 + r0 + 8]       += acc[am][t8][2];
                Gs[(n + 1) * 65 + r0 + 8] += acc[am][t8][3];
            }
    }
    __syncthreads();

    float* c_io  = &g_c[layer][0][0];
    float* h_out = &g_h[layer][parity ^ 1][0][0];
#pragma unroll
    for (int i = 0; i < 4; i++) {
        int idx = tid + i * NTH;   // 0..1023
        int jn  = idx & 15;
        int b   = idx >> 4;
        int j   = j0 + jn;
        float gi = Gs[jn * 65 + b]        + bih[j]          + bhh[j];
        float gf = Gs[(16 + jn) * 65 + b] + bih[H_ + j]     + bhh[H_ + j];
        float gc = Gs[(32 + jn) * 65 + b] + bih[2 * H_ + j] + bhh[2 * H_ + j];
        float go = Gs[(48 + jn) * 65 + b] + bih[3 * H_ + j] + bhh[3 * H_ + j];
        float ii = 1.f / (1.f + expf(-gi));
        float ff = 1.f / (1.f + expf(-gf));
        float gt = tanhf(gc);
        float oo = 1.f / (1.f + expf(-go));
        int   ci = b * H_ + j;
        float c2 = ff * c_io[ci] + ii * gt;
        c_io[ci]  = c2;
        h_out[ci] = oo * tanhf(c2);
    }
}

// FC + hardtanh + feedback. Grid = 16 batch-groups (4 b each) x 6 n-groups
// (11 n each). Each CTA stages its 4 h rows in smem; warps sweep (b, n) dots
// with lanes striding K -> coalesced fcw reads, fcw L2 traffic cut 4x.
__global__ void __launch_bounds__(256, 1)
fc_kernel(const float* __restrict__ fcw, const float* __restrict__ fcb,
          float* __restrict__ out, int hpar, int t) {
    __shared__ __align__(16) float hs[4][H_];
    const int bg = blockIdx.x;          // 0..15  (batches 4*bg .. 4*bg+3)
    const int ng = blockIdx.y;          // 0..5   (outputs 11*ng .. 11*ng+10)
    const int warp = threadIdx.x >> 5, lane = threadIdx.x & 31;

    for (int i = threadIdx.x * 4; i < 4 * H_; i += 256 * 4) {
        int bb = i >> 11;               // H_ = 2048
        int k  = i & (H_ - 1);
        *reinterpret_cast<float4*>(&hs[bb][k]) =
            *reinterpret_cast<const float4*>(&g_h[1][hpar][4 * bg + bb][k]);
    }
    __syncthreads();

    // 44 dots = 4 b x 11 n; warp w handles dots w, w+8, ...
    for (int d = warp; d < 44; d += 8) {
        int bb = d & 3;
        int nn = d >> 2;                // 0..10
        int n  = 11 * ng + nn;
        const float* w = fcw + (size_t)n * H_;
        float s = 0.f;
#pragma unroll
        for (int i = 0; i < 16; i++) {
            int k = i * 128 + lane * 4;
            float4 wv = *reinterpret_cast<const float4*>(w + k);
            float4 hv = *reinterpret_cast<const float4*>(&hs[bb][k]);
            s += wv.x * hv.x + wv.y * hv.y + wv.z * hv.z + wv.w * hv.w;
        }
        s += __shfl_xor_sync(0xffffffffu, s, 16);
        s += __shfl_xor_sync(0xffffffffu, s, 8);
        s += __shfl_xor_sync(0xffffffffu, s, 4);
        s += __shfl_xor_sync(0xffffffffu, s, 2);
        s += __shfl_xor_sync(0xffffffffu, s, 1);
        if (lane == 0) {
            int b = 4 * bg + bb;
            float r = s + fcb[n];
            r = fminf(1.f, fmaxf(-1.f, r));          // hardtanh
            out[(b * T_ + t) * IN_ + n] = r;         // d_out[b][t][n]
            g_x[hpar][b][n] = r;                     // detached feedback
        }
    }
}

// Copy inputs into scratch each launch (determinism: c is updated in place).
__global__ void init_kernel(const float* __restrict__ inputs,
                            const float* __restrict__ hiddens,
                            const float* __restrict__ cells) {
    const int stride = gridDim.x * blockDim.x;
    const int tid0   = blockIdx.x * blockDim.x + threadIdx.x;
    for (int i = tid0; i < 2 * B_ * XPAD; i += stride) {
        int par = i / (B_ * XPAD);
        int rem = i - par * (B_ * XPAD);
        int b = rem / XPAD, k = rem - b * XPAD;
        (&g_x[0][0][0])[i] = (par == 0 && k < IN_) ? inputs[b * IN_ + k] : 0.f;
    }
    for (int i = tid0; i < 2 * B_ * H_; i += stride) {
        int l   = i >> 17;               // B_*H_ = 2^17
        int rem = i & (B_ * H_ - 1);
        (&g_h[l][0][0][0])[rem] = hiddens[i];
        (&g_c[0][0][0])[i]      = cells[i];
    }
}

extern "C" void kernel_launch(void* const* d_in, const int* in_sizes, int n_in,
                              void* d_out, int out_size) {
    const float* inputs  = (const float*)d_in[0];
    const float* hiddens = (const float*)d_in[1];
    const float* cells   = (const float*)d_in[2];
    const float* Wih0 = (const float*)d_in[3];
    const float* Whh0 = (const float*)d_in[4];
    const float* bih0 = (const float*)d_in[5];
    const float* bhh0 = (const float*)d_in[6];
    const float* Wih1 = (const float*)d_in[7];
    const float* Whh1 = (const float*)d_in[8];
    const float* bih1 = (const float*)d_in[9];
    const float* bhh1 = (const float*)d_in[10];
    const float* fcw  = (const float*)d_in[11];
    const float* fcb  = (const float*)d_in[12];
    float* out = (float*)d_out;

    // Opt in to >48KB dynamic smem (idempotent, capture-safe host call).
    cudaFuncSetAttribute(lstm_cell_kernel,
                         cudaFuncAttributeMaxDynamicSharedMemorySize, SMEM_BYTES);

    init_kernel<<<256, 256>>>(inputs, hiddens, cells);
    dim3 fc_grid(16, 6);
    for (int t = 0; t < T_; t++) {
        int p = t & 1;
        lstm_cell_kernel<<<H_ / JT, NTH, SMEM_BYTES>>>(Wih0, Whh0, bih0, bhh0, 0, p, 1);
        lstm_cell_kernel<<<H_ / JT, NTH, SMEM_BYTES>>>(Wih1, Whh1, bih1, bhh1, 1, p, 0);
        fc_kernel<<<fc_grid, 256>>>(fcw, fcb, out, p ^ 1, t);
    }
}

// round 11
// speedup vs baseline: 1.1503x; 1.1503x over previous
#include <cuda_runtime.h>
#include <math.h>

// ---------------------------------------------------------------------------
// Decoder_50775103373422: 2-layer LSTM (B=64, H=2048, IN=OUT=66, T=25) with
// hardtanh output fed back as next input.
// R11: K-split warp tiling (each warp: full m64n64 acc, k16 slice per tile)
//      -> smem crossbar bytes halved (the measured bottleneck).
//      fc: 64 CTAs x 512 threads.
// ---------------------------------------------------------------------------

namespace {
constexpr int B_   = 64;    // batch
constexpr int H_   = 2048;  // hidden
constexpr int IN_  = 66;    // input / output features
constexpr int T_   = 25;    // timesteps
constexpr int XPAD = 72;    // padded input width (multiple of 8)
constexpr int JT   = 16;    // hidden units per CTA  -> grid = 2048/16 = 128
constexpr int SLD  = 76;    // smem row stride in floats (conflict-free)
constexpr int NTH  = 128;   // threads per cell CTA (4 warps, k-split)
constexpr int STG  = 3;     // cp.async pipeline stages
constexpr int TILE_WORDS = B_ * SLD;                       // floats per A or B stage
constexpr int SMEM_BYTES = STG * 2 * TILE_WORDS * 4;       // 116736 B dynamic smem
}

// Scratch state (allocation-free rule: __device__ globals), 16B-aligned
__device__ __align__(16) float g_x[2][B_][XPAD];   // fed-back input, ping-pong
__device__ __align__(16) float g_h[2][2][B_][H_];  // [layer][parity][b][j]
__device__ __align__(16) float g_c[2][B_][H_];     // in-place per launch

__device__ __forceinline__ unsigned u32smem(const void* p) {
    return (unsigned)__cvta_generic_to_shared(p);
}
__device__ __forceinline__ void cpasync16(unsigned s, const void* g) {
    asm volatile("cp.async.cg.shared.global [%0], [%1], 16;\n" :: "r"(s), "l"(g));
}
__device__ __forceinline__ void cpcommit() {
    asm volatile("cp.async.commit_group;\n" ::);
}
template <int N>
__device__ __forceinline__ void cpwait() {
    asm volatile("cp.async.wait_group %0;\n" :: "n"(N));
}

__device__ __forceinline__ void mma8(float* d,
                                     unsigned a0, unsigned a1, unsigned a2, unsigned a3,
                                     unsigned b0, unsigned b1) {
    asm volatile(
        "mma.sync.aligned.m16n8k8.row.col.f32.tf32.tf32.f32 "
        "{%0,%1,%2,%3}, {%4,%5,%6,%7}, {%8,%9}, {%0,%1,%2,%3};"
        : "+f"(d[0]), "+f"(d[1]), "+f"(d[2]), "+f"(d[3])
        : "r"(a0), "r"(a1), "r"(a2), "r"(a3), "r"(b0), "r"(b1));
}

// Issue cp.async for one 64x64 fp32 tile of A and of B into a stage (128 thr).
__device__ __forceinline__ void issue_tile(float* sA, float* sB,
                                           const float* __restrict__ A,
                                           const float* __restrict__ W,
                                           int j0, int k0, int tid) {
    const int r = tid >> 4;            // 0..7
    const int c = (tid & 15) << 2;     // 0..60
#pragma unroll
    for (int p = 0; p < 8; p++) {
        int row = r + p * 8;
        cpasync16(u32smem(sA + row * SLD + c), A + (size_t)row * H_ + k0 + c);
    }
#pragma unroll
    for (int p = 0; p < 8; p++) {
        int n = r + p * 8;
        int R = (n >> 4) * H_ + j0 + (n & 15);   // gate-major weight row
        cpasync16(u32smem(sB + n * SLD + c), W + (size_t)R * H_ + k0 + c);
    }
}

// Warp computes its kb-slice [kb0, kb1) of a tile, FULL m64 x n64 output.
// acc[am][t8][4]: am = m16 frag (rows am*16+gID, +8), t8 = n8 frag.
// As/Bs hold raw fp32 bits; HMMA.TF32 truncates mantissa in hardware.
__device__ __forceinline__ void tile_compute(const unsigned* __restrict__ As,
                                             const unsigned* __restrict__ Bs,
                                             float (&acc)[4][8][4],
                                             int kb0, int kb1, int gID, int tig) {
    for (int kb = kb0; kb < kb1; kb++) {
        const int kk = kb * 8;
        unsigned a[4][4];
#pragma unroll
        for (int am = 0; am < 4; am++) {
            int r0 = (am * 16 + gID) * SLD;
            a[am][0] = As[r0 + kk + tig];
            a[am][1] = As[r0 + 8 * SLD + kk + tig];
            a[am][2] = As[r0 + kk + tig + 4];
            a[am][3] = As[r0 + 8 * SLD + kk + tig + 4];
        }
#pragma unroll
        for (int t8 = 0; t8 < 8; t8++) {
            int n = (t8 * 8 + gID) * SLD;
            unsigned b0 = Bs[n + kk + tig];
            unsigned b1 = Bs[n + kk + tig + 4];
#pragma unroll
            for (int am = 0; am < 4; am++)
                mma8(acc[am][t8], a[am][0], a[am][1], a[am][2], a[am][3], b0, b1);
        }
    }
}

// One LSTM cell step for one layer. CTA owns hidden units [j0, j0+16) across
// all 4 gates (64 N-cols), full batch (M=64). 4 warps k-split each tile;
// epilogue reduces 4 partial m64n64 grids and does the fused cell update.
__global__ void __launch_bounds__(NTH, 1)
lstm_cell_kernel(const float* __restrict__ Wih, const float* __restrict__ Whh,
                 const float* __restrict__ bih, const float* __restrict__ bhh,
                 int layer, int parity, int use_x) {
    extern __shared__ __align__(16) float smem_raw[];
    float* sA[STG];
    float* sB[STG];
#pragma unroll
    for (int st = 0; st < STG; st++) {
        sA[st] = smem_raw + st * 2 * TILE_WORDS;
        sB[st] = sA[st] + TILE_WORDS;
    }

    const int tid  = threadIdx.x;
    const int j0   = blockIdx.x * JT;
    const int warp = tid >> 5, lane = tid & 31;
    const int gID = lane >> 2, tig = lane & 3;

    float acc[4][8][4];
#pragma unroll
    for (int a = 0; a < 4; a++)
#pragma unroll
        for (int b = 0; b < 8; b++)
#pragma unroll
            for (int c = 0; c < 4; c++) acc[a][b][c] = 0.f;

    // ---- layer0 only: x @ Wih0^T  (K=72: 9 kb's split 2/2/2/3) ----
    if (use_x) {
        const float* A = &g_x[parity][0][0];
        for (int idx = tid; idx < B_ * XPAD; idx += NTH) {
            int r = idx / XPAD, k = idx - r * XPAD;
            sA[0][r * SLD + k] = A[idx];
        }
        for (int idx = tid; idx < B_ * XPAD; idx += NTH) {
            int n = idx / XPAD, k = idx - n * XPAD;
            int R = (n >> 4) * H_ + j0 + (n & 15);
            sB[0][n * SLD + k] = (k < IN_) ? Wih[R * IN_ + k] : 0.f;
        }
        __syncthreads();
        int kb0 = 2 * warp;
        int kb1 = (warp == 3) ? 9 : kb0 + 2;
        tile_compute((const unsigned*)sA[0], (const unsigned*)sB[0],
                     acc, kb0, kb1, gID, tig);
        __syncthreads();
    }

    // ---- K=2048 segments, 3-stage cp.async pipeline ----
    const float* Aseg[2];
    const float* Wseg[2];
    int nseg;
    if (use_x) {                                 // layer 0: h0_prev @ Whh0^T
        Aseg[0] = &g_h[0][parity][0][0];     Wseg[0] = Whh;  nseg = 1;
    } else {                                     // layer 1: h0_new @ Wih1^T + h1_prev @ Whh1^T
        Aseg[0] = &g_h[0][parity ^ 1][0][0]; Wseg[0] = Wih;
        Aseg[1] = &g_h[1][parity][0][0];     Wseg[1] = Whh;
        nseg = 2;
    }
    const int total = nseg * 32;
    const int mkb0 = 2 * warp;        // this warp's k16 slice of every tile

    // Prologue: fill STG-1 stages.
#pragma unroll
    for (int s = 0; s < STG - 1; s++) {
        issue_tile(sA[s], sB[s], Aseg[s >> 5], Wseg[s >> 5], j0, (s & 31) * 64, tid);
        cpcommit();
    }

    for (int s = 0; s < total; s++) {
        cpwait<STG - 2>();          // stage s landed
        __syncthreads();
        int nx = s + STG - 1;
        if (nx < total) {
            issue_tile(sA[nx % STG], sB[nx % STG],
                       Aseg[nx >> 5], Wseg[nx >> 5], j0, (nx & 31) * 64, tid);
        }
        cpcommit();                 // keep group accounting aligned
        int cs = s % STG;
        tile_compute((const unsigned*)sA[cs], (const unsigned*)sB[cs],
                     acc, mkb0, mkb0 + 2, gID, tig);
    }
    __syncthreads();

    // ---- epilogue: pairwise reduce 4 partial grids in smem [n][b] ----
    float* G0 = smem_raw;                    // 64 x 65 fp32
    float* G1 = smem_raw + 64 * 65 + 16;     // second buffer
    float* Gw = (warp & 1) ? G1 : G0;
    if (warp < 2) {
#pragma unroll
        for (int am = 0; am < 4; am++)
#pragma unroll
            for (int t8 = 0; t8 < 8; t8++) {
                int r0 = am * 16 + gID;
                int n  = t8 * 8 + (tig << 1);
                Gw[n * 65 + r0]           = acc[am][t8][0];
                Gw[(n + 1) * 65 + r0]     = acc[am][t8][1];
                Gw[n * 65 + r0 + 8]       = acc[am][t8][2];
                Gw[(n + 1) * 65 + r0 + 8] = acc[am][t8][3];
            }
    }
    __syncthreads();
    if (warp >= 2) {
#pragma unroll
        for (int am = 0; am < 4; am++)
#pragma unroll
            for (int t8 = 0; t8 < 8; t8++) {
                int r0 = am * 16 + gID;
                int n  = t8 * 8 + (tig << 1);
                Gw[n * 65 + r0]           += acc[am][t8][0];
                Gw[(n + 1) * 65 + r0]     += acc[am][t8][1];
                Gw[n * 65 + r0 + 8]       += acc[am][t8][2];
                Gw[(n + 1) * 65 + r0 + 8] += acc[am][t8][3];
            }
    }
    __syncthreads();

    float* c_io  = &g_c[layer][0][0];
    float* h_out = &g_h[layer][parity ^ 1][0][0];
#pragma unroll
    for (int i = 0; i < 8; i++) {
        int idx = tid + i * NTH;   // 0..1023
        int jn  = idx & 15;
        int b   = idx >> 4;
        int j   = j0 + jn;
        float gi = G0[jn * 65 + b]        + G1[jn * 65 + b]        + bih[j]          + bhh[j];
        float gf = G0[(16 + jn) * 65 + b] + G1[(16 + jn) * 65 + b] + bih[H_ + j]     + bhh[H_ + j];
        float gc = G0[(32 + jn) * 65 + b] + G1[(32 + jn) * 65 + b] + bih[2 * H_ + j] + bhh[2 * H_ + j];
        float go = G0[(48 + jn) * 65 + b] + G1[(48 + jn) * 65 + b] + bih[3 * H_ + j] + bhh[3 * H_ + j];
        float ii = 1.f / (1.f + expf(-gi));
        float ff = 1.f / (1.f + expf(-gf));
        float gt = tanhf(gc);
        float oo = 1.f / (1.f + expf(-go));
        int   ci = b * H_ + j;
        float c2 = ff * c_io[ci] + ii * gt;
        c_io[ci]  = c2;
        h_out[ci] = oo * tanhf(c2);
    }
}

// FC + hardtanh + feedback. 64 CTAs (one per batch row) x 512 threads:
// h[b] staged once, 16 warps sweep output units with lanes striding K.
__global__ void __launch_bounds__(512, 1)
fc_kernel(const float* __restrict__ fcw, const float* __restrict__ fcb,
          float* __restrict__ out, int hpar, int t) {
    __shared__ __align__(16) float hs[H_];
    const int b = blockIdx.x;
    // 512 threads x one float4 = 2048 floats
    {
        int k = threadIdx.x * 4;
        *reinterpret_cast<float4*>(&hs[k]) =
            *reinterpret_cast<const float4*>(&g_h[1][hpar][b][k]);
    }
    __syncthreads();

    const int warp = threadIdx.x >> 5, lane = threadIdx.x & 31;
    for (int n = warp; n < IN_; n += 16) {
        const float* w = fcw + (size_t)n * H_;
        float s = 0.f;
#pragma unroll
        for (int i = 0; i < 16; i++) {
            int k = i * 128 + lane * 4;
            float4 wv = *reinterpret_cast<const float4*>(w + k);
            float4 hv = *reinterpret_cast<const float4*>(hs + k);
            s += wv.x * hv.x + wv.y * hv.y + wv.z * hv.z + wv.w * hv.w;
        }
        s += __shfl_xor_sync(0xffffffffu, s, 16);
        s += __shfl_xor_sync(0xffffffffu, s, 8);
        s += __shfl_xor_sync(0xffffffffu, s, 4);
        s += __shfl_xor_sync(0xffffffffu, s, 2);
        s += __shfl_xor_sync(0xffffffffu, s, 1);
        if (lane == 0) {
            float r = s + fcb[n];
            r = fminf(1.f, fmaxf(-1.f, r));          // hardtanh
            out[(b * T_ + t) * IN_ + n] = r;         // d_out[b][t][n]
            g_x[hpar][b][n] = r;                     // detached feedback
        }
    }
}

// Copy inputs into scratch each launch (determinism: c is updated in place).
__global__ void init_kernel(const float* __restrict__ inputs,
                            const float* __restrict__ hiddens,
                            const float* __restrict__ cells) {
    const int stride = gridDim.x * blockDim.x;
    const int tid0   = blockIdx.x * blockDim.x + threadIdx.x;
    for (int i = tid0; i < 2 * B_ * XPAD; i += stride) {
        int par = i / (B_ * XPAD);
        int rem = i - par * (B_ * XPAD);
        int b = rem / XPAD, k = rem - b * XPAD;
        (&g_x[0][0][0])[i] = (par == 0 && k < IN_) ? inputs[b * IN_ + k] : 0.f;
    }
    for (int i = tid0; i < 2 * B_ * H_; i += stride) {
        int l   = i >> 17;               // B_*H_ = 2^17
        int rem = i & (B_ * H_ - 1);
        (&g_h[l][0][0][0])[rem] = hiddens[i];
        (&g_c[0][0][0])[i]      = cells[i];
    }
}

extern "C" void kernel_launch(void* const* d_in, const int* in_sizes, int n_in,
                              void* d_out, int out_size) {
    const float* inputs  = (const float*)d_in[0];
    const float* hiddens = (const float*)d_in[1];
    const float* cells   = (const float*)d_in[2];
    const float* Wih0 = (const float*)d_in[3];
    const float* Whh0 = (const float*)d_in[4];
    const float* bih0 = (const float*)d_in[5];
    const float* bhh0 = (const float*)d_in[6];
    const float* Wih1 = (const float*)d_in[7];
    const float* Whh1 = (const float*)d_in[8];
    const float* bih1 = (const float*)d_in[9];
    const float* bhh1 = (const float*)d_in[10];
    const float* fcw  = (const float*)d_in[11];
    const float* fcb  = (const float*)d_in[12];
    float* out = (float*)d_out;

    // Opt in to >48KB dynamic smem (idempotent, capture-safe host call).
    cudaFuncSetAttribute(lstm_cell_kernel,
                         cudaFuncAttributeMaxDynamicSharedMemorySize, SMEM_BYTES);

    init_kernel<<<256, 256>>>(inputs, hiddens, cells);
    for (int t = 0; t < T_; t++) {
        int p = t & 1;
        lstm_cell_kernel<<<H_ / JT, NTH, SMEM_BYTES>>>(Wih0, Whh0, bih0, bhh0, 0, p, 1);
        lstm_cell_kernel<<<H_ / JT, NTH, SMEM_BYTES>>>(Wih1, Whh1, bih1, bhh1, 1, p, 0);
        fc_kernel<<<B_, 512>>>(fcw, fcb, out, p ^ 1, t);
    }
}